// round 12
// baseline (speedup 1.0000x reference)
#include <cuda_runtime.h>
#include <cuda_fp16.h>
#include <cstdint>

#define Bsz 4
#define Tsz 4096
#define Isz 1024
#define Esz 16
#define Ksz 512
#define Jsz 1024

// ---------------- scratch: fp16 operands ----------------
__device__ __half g_WhT[(size_t)Esz * Jsz * Isz];   // W^T [E][J][I]
__device__ __half g_Xh[(size_t)Bsz * Tsz * Isz];    // X   [B][T][I]

// ---------------- helpers ----------------
__device__ __forceinline__ uint32_t smem_u32(const void* p) {
    uint32_t a;
    asm("{ .reg .u64 t; cvta.to.shared.u64 t, %1; cvt.u32.u64 %0, t; }" : "=r"(a) : "l"(p));
    return a;
}
// 64B rows of 4x16B chunks; chunk xor'd by ((row>>1)&3): conflict-free STS/ldsm.
__device__ __forceinline__ uint32_t swzoff(int row, int c) {
    return (uint32_t)(row * 64 + ((c ^ ((row >> 1) & 3)) * 16));
}
__device__ __forceinline__ void ldsm4(uint32_t* r, uint32_t addr) {
    asm volatile("ldmatrix.sync.aligned.m8n8.x4.shared.b16 {%0,%1,%2,%3}, [%4];"
                 : "=r"(r[0]), "=r"(r[1]), "=r"(r[2]), "=r"(r[3]) : "r"(addr));
}
__device__ __forceinline__ void mma16816(float* d, const uint32_t* a, const uint32_t* b) {
    asm volatile("mma.sync.aligned.m16n8k16.row.col.f32.f16.f16.f32 "
                 "{%0,%1,%2,%3},{%4,%5,%6,%7},{%8,%9},{%0,%1,%2,%3};"
                 : "+f"(d[0]), "+f"(d[1]), "+f"(d[2]), "+f"(d[3])
                 : "r"(a[0]), "r"(a[1]), "r"(a[2]), "r"(a[3]), "r"(b[0]), "r"(b[1]));
}
__device__ __forceinline__ void cpasync16(uint32_t dst, const void* src) {
    asm volatile("cp.async.cg.shared.global [%0], [%1], 16;" :: "r"(dst), "l"(src));
}

// ---------------- fused pre-pass: X convert + W transpose/convert ----------------
// blocks [0, XBLK): X fp32 -> fp16 flat
// blocks [XBLK, XBLK+16384): W [E][I][J] fp32 -> W^T fp16 [E][J][I], 32x32 tiles
#define XBLK 8192
__global__ void prep(const float* __restrict__ X, const float* __restrict__ W) {
    __shared__ float tile[32][33];
    const int bid = blockIdx.x;
    const int tid = threadIdx.x;
    if (bid < XBLK) {
        const size_t i = ((size_t)bid * 256 + tid) * 8;
        const float4 v0 = *(const float4*)(X + i);
        const float4 v1 = *(const float4*)(X + i + 4);
        __half2 h0 = __floats2half2_rn(v0.x, v0.y);
        __half2 h1 = __floats2half2_rn(v0.z, v0.w);
        __half2 h2 = __floats2half2_rn(v1.x, v1.y);
        __half2 h3 = __floats2half2_rn(v1.z, v1.w);
        uint4 o = make_uint4(*(uint32_t*)&h0, *(uint32_t*)&h1,
                             *(uint32_t*)&h2, *(uint32_t*)&h3);
        *(uint4*)(g_Xh + i) = o;
    } else {
        const int wi = bid - XBLK;
        const int jb = wi & 31, ib = (wi >> 5) & 31, e = wi >> 10;
        const int i0 = ib * 32, j0 = jb * 32;
        const int tx = tid & 31, ty = tid >> 5;   // 32 x 8
        const float* Wp = W + ((size_t)e * Isz + i0) * Jsz + j0;
        #pragma unroll
        for (int r = 0; r < 4; r++)
            tile[ty + 8 * r][tx] = Wp[(size_t)(ty + 8 * r) * Jsz + tx];
        __syncthreads();
        const size_t ob = ((size_t)e * Jsz + j0) * Isz + i0;
        #pragma unroll
        for (int r = 0; r < 4; r++) {
            const int j = ty + 8 * r;
            g_WhT[ob + (size_t)j * Isz + tx] = __float2half_rn(tile[tx][j]);
        }
    }
}

// ---------------- main: 64x128 tile, 256 threads, 2 CTAs/SM ----------------
#define NT 256
#define STAGE 12288           // A @0 (4KB: 64 rows x 64B), B @4096 (8KB: 128 rows x 64B)
#define NSTG 4
#define SMEM_BYTES (NSTG * STAGE + 512)

__global__ __launch_bounds__(NT, 2)
void moe_gemm(const int* __restrict__ ind, float* __restrict__ Y) {
    extern __shared__ char sm[];
    const uint32_t sbase = smem_u32(sm);
    int* rows = (int*)(sm + NSTG * STAGE);

    const int tid = threadIdx.x;
    const int be = blockIdx.z, b = be >> 4, e = be & 15;
    const int m0 = blockIdx.y * 64, n0 = blockIdx.x * 128;

    if (tid < 64) rows[tid] = ind[((size_t)b * Esz + e) * Ksz + m0 + tid];
    __syncthreads();

    // ---- producer mapping (per 32-k stage)
    // A: 64 rows x 4 chunks = 256 tasks -> 1/thread
    const int arow = tid >> 2;
    const int aq   = tid & 3;
    const uint32_t aoffp = swzoff(arow, aq);
    const __half* xsrc = g_Xh + ((size_t)b * Tsz + rows[arow]) * Isz + aq * 8;
    // B: 128 rows x 4 chunks = 512 tasks -> 2/thread
    const int brow = tid >> 1;
    const int bq0  = (tid & 1) * 2;
    const uint32_t boffp0 = 4096u + swzoff(brow, bq0);
    const uint32_t boffp1 = 4096u + swzoff(brow, bq0 + 1);
    const __half* wsrc = g_WhT + ((size_t)e * Jsz + n0 + brow) * Isz + bq0 * 8;

    // ---- consumer mapping (warp tile 32x32): 2 M-warps x 4 N-warps
    const int lane = tid & 31, w = tid >> 5;
    const int wm = (w & 1) * 32, wn = (w >> 1) * 32;
    uint32_t loffA[2], loffB[2];
    {
        const int chiA = lane >> 4;
        #pragma unroll
        for (int mt = 0; mt < 2; ++mt) {
            const int rowA = wm + mt * 16 + (lane & 7) + ((lane >> 3) & 1) * 8;
            loffA[mt] = swzoff(rowA, chiA);
        }
        const int chiB = (lane >> 3) & 1;
        #pragma unroll
        for (int ng = 0; ng < 2; ++ng) {
            const int rowB = wn + ng * 16 + (lane & 7) + ((lane >> 4) & 1) * 8;
            loffB[ng] = 4096u + swzoff(rowB, chiB);
        }
    }

    float acc[2][4][4];
    #pragma unroll
    for (int i = 0; i < 2; ++i)
        #pragma unroll
        for (int j = 0; j < 4; ++j)
            #pragma unroll
            for (int q = 0; q < 4; ++q) acc[i][j][q] = 0.0f;

    auto issue = [&](int c) {
        const uint32_t stg = sbase + (uint32_t)(c & (NSTG - 1)) * STAGE;
        const int k0 = c * 32;
        cpasync16(stg + aoffp,  xsrc + k0);
        cpasync16(stg + boffp0, wsrc + k0);
        cpasync16(stg + boffp1, wsrc + k0 + 8);
    };

    #pragma unroll
    for (int s = 0; s < NSTG - 1; ++s) {
        issue(s);
        asm volatile("cp.async.commit_group;" ::: "memory");
    }

    for (int c = 0; c < 32; ++c) {
        asm volatile("cp.async.wait_group %0;" :: "n"(NSTG - 2) : "memory");
        __syncthreads();

        if (c + NSTG - 1 < 32) issue(c + NSTG - 1);
        asm volatile("cp.async.commit_group;" ::: "memory");

        const uint32_t stg = sbase + (uint32_t)(c & (NSTG - 1)) * STAGE;

        #pragma unroll
        for (int ks = 0; ks < 2; ++ks) {
            const uint32_t kx = (uint32_t)ks << 5;
            uint32_t a[2][4], bb[2][4];
            #pragma unroll
            for (int mt = 0; mt < 2; ++mt)
                ldsm4(a[mt], stg + (loffA[mt] ^ kx));
            #pragma unroll
            for (int ng = 0; ng < 2; ++ng)
                ldsm4(bb[ng], stg + (loffB[ng] ^ kx));
            #pragma unroll
            for (int mt = 0; mt < 2; ++mt)
                #pragma unroll
                for (int ng = 0; ng < 2; ++ng) {
                    mma16816(acc[mt][2 * ng],     a[mt], bb[ng]);
                    mma16816(acc[mt][2 * ng + 1], a[mt], bb[ng] + 2);
                }
        }
    }

    // ---- epilogue
    float* Yb = Y + ((size_t)be * Ksz + m0) * Jsz + n0;
    #pragma unroll
    for (int mt = 0; mt < 2; ++mt) {
        const int row = wm + mt * 16 + (lane >> 2);
        #pragma unroll
        for (int j = 0; j < 4; ++j) {
            const int col = wn + j * 8 + (lane & 3) * 2;
            *(float2*)&Yb[(size_t)row * Jsz + col] =
                make_float2(acc[mt][j][0], acc[mt][j][1]);
            *(float2*)&Yb[(size_t)(row + 8) * Jsz + col] =
                make_float2(acc[mt][j][2], acc[mt][j][3]);
        }
    }
}

// ---------------- launch ----------------
extern "C" void kernel_launch(void* const* d_in, const int* in_sizes, int n_in,
                              void* d_out, int out_size) {
    const float* X   = (const float*)d_in[0];
    const int*   ind = (const int*)d_in[1];
    const float* W   = (const float*)d_in[2];
    float*       Y   = (float*)d_out;

    cudaFuncSetAttribute(moe_gemm, cudaFuncAttributeMaxDynamicSharedMemorySize, SMEM_BYTES);

    prep<<<XBLK + 16384, 256>>>(X, W);

    dim3 grid(Jsz / 128, Ksz / 64, Bsz * Esz);   // (8, 8, 64) = 4096 CTAs
    moe_gemm<<<grid, NT, SMEM_BYTES>>>(ind, Y);
}

// round 13
// speedup vs baseline: 1.0862x; 1.0862x over previous
#include <cuda_runtime.h>
#include <cuda_fp16.h>
#include <cstdint>

#define Bsz 4
#define Tsz 4096
#define Isz 1024
#define Esz 16
#define Ksz 512
#define Jsz 1024

// ---------------- scratch: fp16 operands ----------------
__device__ __half g_WhT[(size_t)Esz * Jsz * Isz];   // W^T [E][J][I]
__device__ __half g_Xh[(size_t)Bsz * Tsz * Isz];    // X   [B][T][I]

// ---------------- helpers ----------------
__device__ __forceinline__ uint32_t smem_u32(const void* p) {
    uint32_t a;
    asm("{ .reg .u64 t; cvta.to.shared.u64 t, %1; cvt.u32.u64 %0, t; }" : "=r"(a) : "l"(p));
    return a;
}
// 64B rows of 4x16B chunks; chunk xor'd by ((row>>1)&3): conflict-free STS/ldsm.
__device__ __forceinline__ uint32_t swzoff(int row, int c) {
    return (uint32_t)(row * 64 + ((c ^ ((row >> 1) & 3)) * 16));
}
__device__ __forceinline__ void ldsm4(uint32_t* r, uint32_t addr) {
    asm volatile("ldmatrix.sync.aligned.m8n8.x4.shared.b16 {%0,%1,%2,%3}, [%4];"
                 : "=r"(r[0]), "=r"(r[1]), "=r"(r[2]), "=r"(r[3]) : "r"(addr));
}
__device__ __forceinline__ void mma16816(float* d, const uint32_t* a, const uint32_t* b) {
    asm volatile("mma.sync.aligned.m16n8k16.row.col.f32.f16.f16.f32 "
                 "{%0,%1,%2,%3},{%4,%5,%6,%7},{%8,%9},{%0,%1,%2,%3};"
                 : "+f"(d[0]), "+f"(d[1]), "+f"(d[2]), "+f"(d[3])
                 : "r"(a[0]), "r"(a[1]), "r"(a[2]), "r"(a[3]), "r"(b[0]), "r"(b[1]));
}
__device__ __forceinline__ void cpasync16(uint32_t dst, const void* src) {
    asm volatile("cp.async.cg.shared.global [%0], [%1], 16;" :: "r"(dst), "l"(src));
}

// ---------------- fused pre-pass: X convert + W transpose/convert ----------------
#define XBLK 8192
__global__ void prep(const float* __restrict__ X, const float* __restrict__ W) {
    __shared__ float tile[32][33];
    const int bid = blockIdx.x;
    const int tid = threadIdx.x;
    if (bid < XBLK) {
        const size_t i = ((size_t)bid * 256 + tid) * 8;
        const float4 v0 = *(const float4*)(X + i);
        const float4 v1 = *(const float4*)(X + i + 4);
        __half2 h0 = __floats2half2_rn(v0.x, v0.y);
        __half2 h1 = __floats2half2_rn(v0.z, v0.w);
        __half2 h2 = __floats2half2_rn(v1.x, v1.y);
        __half2 h3 = __floats2half2_rn(v1.z, v1.w);
        uint4 o = make_uint4(*(uint32_t*)&h0, *(uint32_t*)&h1,
                             *(uint32_t*)&h2, *(uint32_t*)&h3);
        *(uint4*)(g_Xh + i) = o;
    } else {
        const int wi = bid - XBLK;
        const int jb = wi & 31, ib = (wi >> 5) & 31, e = wi >> 10;
        const int i0 = ib * 32, j0 = jb * 32;
        const int tx = tid & 31, ty = tid >> 5;   // 32 x 8
        const float* Wp = W + ((size_t)e * Isz + i0) * Jsz + j0;
        #pragma unroll
        for (int r = 0; r < 4; r++)
            tile[ty + 8 * r][tx] = Wp[(size_t)(ty + 8 * r) * Jsz + tx];
        __syncthreads();
        const size_t ob = ((size_t)e * Jsz + j0) * Isz + i0;
        #pragma unroll
        for (int r = 0; r < 4; r++) {
            const int j = ty + 8 * r;
            g_WhT[ob + (size_t)j * Isz + tx] = __float2half_rn(tile[tx][j]);
        }
    }
}

// ---------------- main: 128x256 tile, 256 threads, warp tile 64x64 ----------------
#define NT 256
#define STAGE 24576           // A @0 (8KB: 128 rows x 64B), B @8192 (16KB: 256 rows x 64B)
#define NSTG 4
#define SMEM_BYTES (NSTG * STAGE + 1024)

__global__ __launch_bounds__(NT, 1)
void moe_gemm(const int* __restrict__ ind, float* __restrict__ Y) {
    extern __shared__ char sm[];
    const uint32_t sbase = smem_u32(sm);
    int* rows = (int*)(sm + NSTG * STAGE);

    const int tid = threadIdx.x;
    const int be = blockIdx.z, b = be >> 4, e = be & 15;
    const int m0 = blockIdx.y * 128, n0 = blockIdx.x * 256;

    if (tid < 128) rows[tid] = ind[((size_t)b * Esz + e) * Ksz + m0 + tid];
    __syncthreads();

    // ---- producer mapping (per 32-k stage)
    // A: 128 rows x 4 chunks = 512 tasks -> 2/thread (rows t>>2 and 64+(t>>2))
    const int arow = tid >> 2;
    const int aq   = tid & 3;
    const uint32_t aoff0 = swzoff(arow, aq);
    const uint32_t aoff1 = swzoff(arow + 64, aq);
    const __half* xsrc0 = g_Xh + ((size_t)b * Tsz + rows[arow]) * Isz + aq * 8;
    const __half* xsrc1 = g_Xh + ((size_t)b * Tsz + rows[arow + 64]) * Isz + aq * 8;
    // B: 256 rows x 4 chunks = 1024 tasks -> 4/thread (row t>>1, t>>1+128; chunks 2(t&1),+1)
    const int brow = tid >> 1;
    const int bq0  = (tid & 1) * 2;
    const uint32_t boff0 = 8192u + swzoff(brow, bq0);
    const uint32_t boff1 = 8192u + swzoff(brow, bq0 + 1);
    const uint32_t boff2 = 8192u + swzoff(brow + 128, bq0);
    const uint32_t boff3 = 8192u + swzoff(brow + 128, bq0 + 1);
    const __half* wsrc0 = g_WhT + ((size_t)e * Jsz + n0 + brow) * Isz + bq0 * 8;
    const __half* wsrc1 = g_WhT + ((size_t)e * Jsz + n0 + brow + 128) * Isz + bq0 * 8;

    // ---- consumer mapping (warp tile 64x64): 2 M-warps x 4 N-warps
    const int lane = tid & 31, w = tid >> 5;
    const int wm = (w & 1) * 64, wn = (w >> 1) * 64;
    uint32_t loffA[4], loffB[4];
    {
        const int chiA = lane >> 4;
        #pragma unroll
        for (int mt = 0; mt < 4; ++mt) {
            const int rowA = wm + mt * 16 + (lane & 7) + ((lane >> 3) & 1) * 8;
            loffA[mt] = swzoff(rowA, chiA);
        }
        const int chiB = (lane >> 3) & 1;
        #pragma unroll
        for (int ng = 0; ng < 4; ++ng) {
            const int rowB = wn + ng * 16 + (lane & 7) + ((lane >> 4) & 1) * 8;
            loffB[ng] = 8192u + swzoff(rowB, chiB);
        }
    }

    float acc[4][8][4];
    #pragma unroll
    for (int i = 0; i < 4; ++i)
        #pragma unroll
        for (int j = 0; j < 8; ++j)
            #pragma unroll
            for (int q = 0; q < 4; ++q) acc[i][j][q] = 0.0f;

    auto issue = [&](int c) {
        const uint32_t stg = sbase + (uint32_t)(c & (NSTG - 1)) * STAGE;
        const int k0 = c * 32;
        cpasync16(stg + aoff0, xsrc0 + k0);
        cpasync16(stg + aoff1, xsrc1 + k0);
        cpasync16(stg + boff0, wsrc0 + k0);
        cpasync16(stg + boff1, wsrc0 + k0 + 8);
        cpasync16(stg + boff2, wsrc1 + k0);
        cpasync16(stg + boff3, wsrc1 + k0 + 8);
    };

    #pragma unroll
    for (int s = 0; s < NSTG - 1; ++s) {
        issue(s);
        asm volatile("cp.async.commit_group;" ::: "memory");
    }

    for (int c = 0; c < 32; ++c) {
        asm volatile("cp.async.wait_group %0;" :: "n"(NSTG - 2) : "memory");
        __syncthreads();

        if (c + NSTG - 1 < 32) issue(c + NSTG - 1);
        asm volatile("cp.async.commit_group;" ::: "memory");

        const uint32_t stg = sbase + (uint32_t)(c & (NSTG - 1)) * STAGE;

        #pragma unroll
        for (int ks = 0; ks < 2; ++ks) {
            const uint32_t kx = (uint32_t)ks << 5;
            uint32_t a[4][4], bb[4][4];
            #pragma unroll
            for (int mt = 0; mt < 4; ++mt)
                ldsm4(a[mt], stg + (loffA[mt] ^ kx));
            #pragma unroll
            for (int ng = 0; ng < 4; ++ng)
                ldsm4(bb[ng], stg + (loffB[ng] ^ kx));
            #pragma unroll
            for (int mt = 0; mt < 4; ++mt)
                #pragma unroll
                for (int ng = 0; ng < 4; ++ng) {
                    mma16816(acc[mt][2 * ng],     a[mt], bb[ng]);
                    mma16816(acc[mt][2 * ng + 1], a[mt], bb[ng] + 2);
                }
        }
    }

    // ---- epilogue
    float* Yb = Y + ((size_t)be * Ksz + m0) * Jsz + n0;
    #pragma unroll
    for (int mt = 0; mt < 4; ++mt) {
        const int row = wm + mt * 16 + (lane >> 2);
        #pragma unroll
        for (int j = 0; j < 8; ++j) {
            const int col = wn + j * 8 + (lane & 3) * 2;
            *(float2*)&Yb[(size_t)row * Jsz + col] =
                make_float2(acc[mt][j][0], acc[mt][j][1]);
            *(float2*)&Yb[(size_t)(row + 8) * Jsz + col] =
                make_float2(acc[mt][j][2], acc[mt][j][3]);
        }
    }
}

// ---------------- launch ----------------
extern "C" void kernel_launch(void* const* d_in, const int* in_sizes, int n_in,
                              void* d_out, int out_size) {
    const float* X   = (const float*)d_in[0];
    const int*   ind = (const int*)d_in[1];
    const float* W   = (const float*)d_in[2];
    float*       Y   = (float*)d_out;

    cudaFuncSetAttribute(moe_gemm, cudaFuncAttributeMaxDynamicSharedMemorySize, SMEM_BYTES);

    prep<<<XBLK + 16384, 256>>>(X, W);

    dim3 grid(Jsz / 256, Ksz / 128, Bsz * Esz);   // (4, 4, 64) = 1024 CTAs
    moe_gemm<<<grid, NT, SMEM_BYTES>>>(ind, Y);
}